// round 12
// baseline (speedup 1.0000x reference)
#include <cuda_runtime.h>
#include <cuda_bf16.h>
#include <math.h>

// Problem constants
static const int BB   = 16;
static const int CC   = 256;
static const int SS   = 1024;   // 32*32
static const int NH   = 8;
static const int DKk  = 32;
static const int GR   = 8;
static const int TDIM = 512;
static const int CDIM = 128;
static const int INDIM = 640;   // TDIM + CDIM
static const int TWOC = 512;

// ---- tf32 / bf16 / ldmatrix / cp.async helpers ----
__device__ __forceinline__ unsigned to_tf32(float f) {
    unsigned r; asm("cvt.rna.tf32.f32 %0, %1;" : "=r"(r) : "f"(f)); return r;
}
__device__ __forceinline__ unsigned cvt2(float hi, float lo) {
    unsigned r;
    asm("cvt.rn.bf16x2.f32 %0, %1, %2;" : "=r"(r) : "f"(hi), "f"(lo));
    return r;
}
__device__ __forceinline__ float ex2f(float x) {
    float y; asm("ex2.approx.ftz.f32 %0, %1;" : "=f"(y) : "f"(x)); return y;
}
__device__ __forceinline__ unsigned s2u(const void* p) {
    return (unsigned)__cvta_generic_to_shared(p);
}
__device__ __forceinline__ void cp16(unsigned dst, const void* src) {
    asm volatile("cp.async.cg.shared.global [%0], [%1], 16;" :: "r"(dst), "l"(src));
}
__device__ __forceinline__ void ldsm4(unsigned& r0, unsigned& r1,
                                      unsigned& r2, unsigned& r3, unsigned a) {
    asm volatile("ldmatrix.sync.aligned.m8n8.x4.shared.b16 {%0,%1,%2,%3}, [%4];"
                 : "=r"(r0), "=r"(r1), "=r"(r2), "=r"(r3) : "r"(a));
}
__device__ __forceinline__ void mma_tf32(float& d0, float& d1, float& d2, float& d3,
                                         unsigned a0, unsigned a1, unsigned a2, unsigned a3,
                                         unsigned b0, unsigned b1) {
    asm("mma.sync.aligned.m16n8k8.row.col.f32.tf32.tf32.f32 "
        "{%0,%1,%2,%3}, {%4,%5,%6,%7}, {%8,%9}, {%0,%1,%2,%3};"
        : "+f"(d0), "+f"(d1), "+f"(d2), "+f"(d3)
        : "r"(a0), "r"(a1), "r"(a2), "r"(a3), "r"(b0), "r"(b1));
}
__device__ __forceinline__ void mma_bf16(float& d0, float& d1, float& d2, float& d3,
                                         unsigned a0, unsigned a1, unsigned a2, unsigned a3,
                                         unsigned b0, unsigned b1) {
    asm("mma.sync.aligned.m16n8k16.row.col.f32.bf16.bf16.f32 "
        "{%0,%1,%2,%3}, {%4,%5,%6,%7}, {%8,%9}, {%0,%1,%2,%3};"
        : "+f"(d0), "+f"(d1), "+f"(d2), "+f"(d3)
        : "r"(a0), "r"(a1), "r"(a2), "r"(a3), "r"(b0), "r"(b1));
}

// Device scratch
__device__ float g_params[BB * TWOC];
__device__ float g_mean[BB * GR];
__device__ float g_rstd[BB * GR];
__device__ float g_xn[BB * SS * CC];
__device__ unsigned g_q[BB * NH * SS * DKk];        // tf32 bits, pre-scaled
__device__ unsigned g_k[BB * NH * SS * DKk];        // tf32 bits
__device__ __nv_bfloat16 g_vt[BB * NH * DKk * SS];  // bf16, d-major: [(bh*32+d)*1024+s]
__device__ float g_att[BB * SS * CC];               // (b, s, c)

// ---------------------------------------------------------------------------
// K1: adaLN projection. grid = 16, block = 640
// ---------------------------------------------------------------------------
__global__ void k_adaln(const float* __restrict__ t_emb,
                        const float* __restrict__ c_emb,
                        const float* __restrict__ pw,
                        const float* __restrict__ pb) {
    __shared__ float sin_[INDIM];
    int b = blockIdx.x;
    int t = threadIdx.x;
    float v = (t < TDIM) ? t_emb[b * TDIM + t] : c_emb[b * CDIM + (t - TDIM)];
    sin_[t] = v / (1.0f + expf(-v));
    __syncthreads();
    if (t < TWOC) {
        const float* wr = pw + t * INDIM;
        float acc = pb[t];
#pragma unroll 8
        for (int i = 0; i < INDIM; i++) acc += sin_[i] * wr[i];
        g_params[b * TWOC + t] = acc;
    }
}

// ---------------------------------------------------------------------------
// K2: GroupNorm statistics. grid = 128, block = 256
// ---------------------------------------------------------------------------
__global__ void k_gnstat(const float* __restrict__ x) {
    int bg = blockIdx.x;
    const float4* p = (const float4*)(x + (size_t)bg * 32768);
    float s = 0.0f, ss = 0.0f;
    for (int i = threadIdx.x; i < 8192; i += 256) {
        float4 v = p[i];
        s  += v.x + v.y + v.z + v.w;
        ss += v.x * v.x + v.y * v.y + v.z * v.z + v.w * v.w;
    }
#pragma unroll
    for (int o = 16; o; o >>= 1) {
        s  += __shfl_xor_sync(0xffffffffu, s, o);
        ss += __shfl_xor_sync(0xffffffffu, ss, o);
    }
    __shared__ float rs[8], rss[8];
    int w = threadIdx.x >> 5, l = threadIdx.x & 31;
    if (l == 0) { rs[w] = s; rss[w] = ss; }
    __syncthreads();
    if (threadIdx.x == 0) {
        float S = 0.0f, SSum = 0.0f;
#pragma unroll
        for (int i = 0; i < 8; i++) { S += rs[i]; SSum += rss[i]; }
        float m = S / 32768.0f;
        float var = SSum / 32768.0f - m * m;
        g_mean[bg] = m;
        g_rstd[bg] = rsqrtf(var + 1e-6f);
    }
}

// ---------------------------------------------------------------------------
// K3: apply GN + adaLN affine, transpose (b,c,s) -> (b,s,c).
// ---------------------------------------------------------------------------
__global__ void k_gnapply(const float* __restrict__ x,
                          const float* __restrict__ gw,
                          const float* __restrict__ gb) {
    __shared__ float tile[CC][33];
    int b = blockIdx.y;
    int s0 = blockIdx.x * 32;
    int t = threadIdx.x;
    int w = t >> 5, sl = t & 31;
#pragma unroll
    for (int k = 0; k < 32; k++) {
        int c = k * 8 + w;
        float v = x[(b * CC + c) * SS + s0 + sl];
        int g = c >> 5;
        float vn = (v - g_mean[b * GR + g]) * g_rstd[b * GR + g];
        vn = vn * gw[c] + gb[c];
        float gam = g_params[b * TWOC + c];
        float bet = g_params[b * TWOC + CC + c];
        tile[c][sl] = vn * (1.0f + gam) + bet;
    }
    __syncthreads();
#pragma unroll
    for (int k = 0; k < 32; k++) {
        g_xn[(b * SS + s0 + k) * CC + t] = tile[t][k];
    }
}

// ---------------------------------------------------------------------------
// K4: QKV GEMM, bf16 m16n8k16 + ldmatrix. Epilogue pre-converts:
// Q -> tf32 bits pre-scaled by (1/sqrt(d))*log2(e); K -> tf32 bits;
// V -> bf16 transposed d-major (g_vt). grid = (6, 128)
// ---------------------------------------------------------------------------
__global__ void __launch_bounds__(256) k_qkv(const float* __restrict__ w,
                                             const float* __restrict__ bias) {
    __shared__ unsigned Ap[128][20];
    __shared__ unsigned Bp[128][20];
    int m0 = blockIdx.y * 128;
    int o0 = blockIdx.x * 128;
    int tid = threadIdx.x;
    int wid = tid >> 5, lane = tid & 31;
    int gid = lane >> 2, tig = lane & 3;
    int wr = wid & 3, wc = wid >> 2;
    int lm = lane >> 3, lr = lane & 7;

    unsigned aBase = s2u(&Ap[0][0]);
    unsigned bBase = s2u(&Bp[0][0]);
    int aRow = wr * 32 + (lm & 1) * 8 + lr;
    int aCol = 4 * (lm >> 1);
    int bRow = wc * 64 + (lm >> 1) * 8 + lr;
    int bCol = 4 * (lm & 1);

    float acc[2][8][4];
#pragma unroll
    for (int mt = 0; mt < 2; mt++)
#pragma unroll
        for (int nt = 0; nt < 8; nt++)
#pragma unroll
            for (int i = 0; i < 4; i++) acc[mt][nt][i] = 0.0f;

    for (int k0 = 0; k0 < 256; k0 += 32) {
        __syncthreads();
#pragma unroll
        for (int i = 0; i < 4; i++) {
            int idx = tid + i * 256;
            int row = idx >> 3, q = idx & 7;
            float4 v = *(const float4*)&g_xn[(m0 + row) * 256 + k0 + q * 4];
            *(uint2*)&Ap[row][2 * q] = make_uint2(cvt2(v.y, v.x), cvt2(v.w, v.z));
            float4 u = *(const float4*)&w[(o0 + row) * 256 + k0 + q * 4];
            *(uint2*)&Bp[row][2 * q] = make_uint2(cvt2(u.y, u.x), cvt2(u.w, u.z));
        }
        __syncthreads();

#pragma unroll
        for (int dk = 0; dk < 2; dk++) {
            unsigned af[2][4];
#pragma unroll
            for (int mt = 0; mt < 2; mt++)
                ldsm4(af[mt][0], af[mt][1], af[mt][2], af[mt][3],
                      aBase + 4u * ((aRow + mt * 16) * 20 + 8 * dk + aCol));
#pragma unroll
            for (int np = 0; np < 4; np++) {
                unsigned b0a, b1a, b0b, b1b;
                ldsm4(b0a, b1a, b0b, b1b,
                      bBase + 4u * ((bRow + np * 16) * 20 + 8 * dk + bCol));
#pragma unroll
                for (int mt = 0; mt < 2; mt++) {
                    mma_bf16(acc[mt][2 * np][0], acc[mt][2 * np][1],
                             acc[mt][2 * np][2], acc[mt][2 * np][3],
                             af[mt][0], af[mt][1], af[mt][2], af[mt][3], b0a, b1a);
                    mma_bf16(acc[mt][2 * np + 1][0], acc[mt][2 * np + 1][1],
                             acc[mt][2 * np + 1][2], acc[mt][2 * np + 1][3],
                             af[mt][0], af[mt][1], af[mt][2], af[mt][3], b0b, b1b);
                }
            }
        }
    }

    int b = m0 >> 10;
    const float qsc = 0.17677669529663687f * 1.4426950408889634f;
#pragma unroll
    for (int mt = 0; mt < 2; mt++) {
        int s_0 = (m0 + wr * 32 + mt * 16 + gid) & 1023;
        int s_1 = s_0 + 8;
#pragma unroll
        for (int nt = 0; nt < 8; nt++) {
            int bcol = wc * 64 + nt * 8 + 2 * tig;   // 0..127
            float bx = bias[o0 + bcol];
            float by = bias[o0 + bcol + 1];
            float v00 = acc[mt][nt][0] + bx, v01 = acc[mt][nt][1] + by;
            float v10 = acc[mt][nt][2] + bx, v11 = acc[mt][nt][3] + by;
            if (o0 < 256) {
                int lcol = o0 + bcol;
                int h = lcol >> 5, d = lcol & 31;
                uint2 u0 = make_uint2(to_tf32(v00 * qsc), to_tf32(v01 * qsc));
                uint2 u1 = make_uint2(to_tf32(v10 * qsc), to_tf32(v11 * qsc));
                *(uint2*)&g_q[((b * 8 + h) * 1024 + s_0) * 32 + d] = u0;
                *(uint2*)&g_q[((b * 8 + h) * 1024 + s_1) * 32 + d] = u1;
            } else if (o0 < 512) {
                int lcol = o0 - 256 + bcol;
                int h = lcol >> 5, d = lcol & 31;
                uint2 u0 = make_uint2(to_tf32(v00), to_tf32(v01));
                uint2 u1 = make_uint2(to_tf32(v10), to_tf32(v11));
                *(uint2*)&g_k[((b * 8 + h) * 1024 + s_0) * 32 + d] = u0;
                *(uint2*)&g_k[((b * 8 + h) * 1024 + s_1) * 32 + d] = u1;
            } else {
                int lcol = o0 - 512 + bcol;
                int h = lcol >> 5, d = lcol & 31;
                int rb = ((b * 8 + h) * 32 + d) * 1024;
                g_vt[rb + s_0]        = __float2bfloat16(v00);
                g_vt[rb + 1024 + s_0] = __float2bfloat16(v01);
                g_vt[rb + s_1]        = __float2bfloat16(v10);
                g_vt[rb + 1024 + s_1] = __float2bfloat16(v11);
            }
        }
    }
}

// ---------------------------------------------------------------------------
// K5: flash attention, cp.async double-buffered K/V, pre-converted operands.
// Phase A tf32 + ldmatrix; base-2 softmax; Phase C bf16 with register P and
// d-major V (direct conflict-free LDS). grid = (128 bh, 8 q), 256 thr.
// Dynamic smem: qs 128x36 | ks 2x128x36 | vs 2x32x68 = 72704 B.
// ---------------------------------------------------------------------------
static const int QS_OFF = 0;
static const int KS_OFF = 4608;
static const int VS_OFF = 13824;
static const int SMEM_ATTN = (13824 + 2 * 2176) * 4;  // 72704 bytes

__device__ __forceinline__ void stage_kv(unsigned ksb, unsigned vsb,
                                         const unsigned* gk,
                                         const __nv_bfloat16* gvt,
                                         int j0, int tid) {
#pragma unroll
    for (int i = 0; i < 4; i++) {
        int idx = tid + i * 256;
        int row = idx >> 3, c = idx & 7;
        cp16(ksb + 4u * (row * 36 + c * 4), gk + (j0 + row) * 32 + c * 4);
    }
#pragma unroll
    for (int i = 0; i < 2; i++) {
        int it = tid + i * 256;
        int d = it >> 4, c = it & 15;
        cp16(vsb + 4u * (d * 68 + c * 4),
             (const char*)gvt + 2 * (d * 1024 + j0) + c * 16);
    }
}

__global__ void __launch_bounds__(256) k_attn() {
    extern __shared__ unsigned smu[];
    unsigned (*qs)[36] = (unsigned(*)[36])(smu + QS_OFF);
    unsigned smuBase = s2u(smu);

    int bh = blockIdx.x;
    int m0 = blockIdx.y * 128;
    int tid = threadIdx.x;
    int w = tid >> 5, lane = tid & 31;
    int gid = lane >> 2, tig = lane & 3;
    int lm = lane >> 3, lr = lane & 7;
    const unsigned* gq = g_q + bh * 32768;
    const unsigned* gk = g_k + bh * 32768;
    const __nv_bfloat16* gvt = g_vt + bh * 32768;
    int r0 = 16 * w + gid;
    int r1 = r0 + 8;

    unsigned ksB[2] = {smuBase + 4u * KS_OFF, smuBase + 4u * (KS_OFF + 4608)};
    unsigned vsB[2] = {smuBase + 4u * VS_OFF, smuBase + 4u * (VS_OFF + 2176)};
    const unsigned* vsP[2] = {smu + VS_OFF, smu + VS_OFF + 2176};
    int kRow = 8 * (lm >> 1) + lr;
    int kCol = 4 * (lm & 1);

    // Prologue: Q copy + tiles 0,1 via cp.async
#pragma unroll
    for (int i = 0; i < 4; i++) {
        int idx = tid + i * 256;
        int row = idx >> 3, c = idx & 7;
        cp16(smuBase + 4u * (row * 36 + c * 4), gq + (m0 + row) * 32 + c * 4);
    }
    stage_kv(ksB[0], vsB[0], gk, gvt, 0, tid);
    asm volatile("cp.async.commit_group;");
    stage_kv(ksB[1], vsB[1], gk, gvt, 128, tid);
    asm volatile("cp.async.commit_group;");
    asm volatile("cp.async.wait_group 1;");
    __syncthreads();

    unsigned qa[4][4];
#pragma unroll
    for (int dk = 0; dk < 4; dk++) {
        qa[dk][0] = qs[r0][8 * dk + tig];
        qa[dk][1] = qs[r1][8 * dk + tig];
        qa[dk][2] = qs[r0][8 * dk + tig + 4];
        qa[dk][3] = qs[r1][8 * dk + tig + 4];
    }

    float m_0 = -1e30f, m_1 = -1e30f, l_0 = 0.0f, l_1 = 0.0f;
    float oacc[4][4];
#pragma unroll
    for (int dn = 0; dn < 4; dn++)
#pragma unroll
        for (int i = 0; i < 4; i++) oacc[dn][i] = 0.0f;

    for (int jt = 0; jt < 8; jt++) {
        int buf = jt & 1;
        unsigned ksb = ksB[buf];
        const unsigned* vsb = vsP[buf];

        // Phase A: S = Q K^T (tf32, ldmatrix K fragments)
        float accS[16][4];
#pragma unroll
        for (int jp = 0; jp < 8; jp++) {
            int ja = 2 * jp, jb = 2 * jp + 1;
            accS[ja][0] = accS[ja][1] = accS[ja][2] = accS[ja][3] = 0.0f;
            accS[jb][0] = accS[jb][1] = accS[jb][2] = accS[jb][3] = 0.0f;
#pragma unroll
            for (int dk = 0; dk < 4; dk++) {
                unsigned b0a, b1a, b0b, b1b;
                ldsm4(b0a, b1a, b0b, b1b,
                      ksb + 4u * ((16 * jp + kRow) * 36 + 8 * dk + kCol));
                mma_tf32(accS[ja][0], accS[ja][1], accS[ja][2], accS[ja][3],
                         qa[dk][0], qa[dk][1], qa[dk][2], qa[dk][3], b0a, b1a);
                mma_tf32(accS[jb][0], accS[jb][1], accS[jb][2], accS[jb][3],
                         qa[dk][0], qa[dk][1], qa[dk][2], qa[dk][3], b0b, b1b);
            }
        }

        // Phase B: online softmax, base 2 (Q carries log2e)
        float mx0 = -1e30f, mx1 = -1e30f;
#pragma unroll
        for (int jn = 0; jn < 16; jn++) {
            mx0 = fmaxf(mx0, fmaxf(accS[jn][0], accS[jn][1]));
            mx1 = fmaxf(mx1, fmaxf(accS[jn][2], accS[jn][3]));
        }
        mx0 = fmaxf(mx0, __shfl_xor_sync(0xffffffffu, mx0, 1));
        mx0 = fmaxf(mx0, __shfl_xor_sync(0xffffffffu, mx0, 2));
        mx1 = fmaxf(mx1, __shfl_xor_sync(0xffffffffu, mx1, 1));
        mx1 = fmaxf(mx1, __shfl_xor_sync(0xffffffffu, mx1, 2));
        float mn0 = fmaxf(m_0, mx0), mn1 = fmaxf(m_1, mx1);
        float corr0 = ex2f(m_0 - mn0), corr1 = ex2f(m_1 - mn1);
        float sum0 = 0.0f, sum1 = 0.0f;
#pragma unroll
        for (int jn = 0; jn < 16; jn++) {
            float p00 = ex2f(accS[jn][0] - mn0);
            float p01 = ex2f(accS[jn][1] - mn0);
            float p10 = ex2f(accS[jn][2] - mn1);
            float p11 = ex2f(accS[jn][3] - mn1);
            sum0 += p00 + p01;
            sum1 += p10 + p11;
            accS[jn][0] = p00; accS[jn][1] = p01;
            accS[jn][2] = p10; accS[jn][3] = p11;
        }
        sum0 += __shfl_xor_sync(0xffffffffu, sum0, 1);
        sum0 += __shfl_xor_sync(0xffffffffu, sum0, 2);
        sum1 += __shfl_xor_sync(0xffffffffu, sum1, 1);
        sum1 += __shfl_xor_sync(0xffffffffu, sum1, 2);
        l_0 = l_0 * corr0 + sum0;
        l_1 = l_1 * corr1 + sum1;
        m_0 = mn0; m_1 = mn1;
#pragma unroll
        for (int dn = 0; dn < 4; dn++) {
            oacc[dn][0] *= corr0; oacc[dn][1] *= corr0;
            oacc[dn][2] *= corr1; oacc[dn][3] *= corr1;
        }

        // Phase C: O += P V (bf16, P in registers, d-major V)
#pragma unroll
        for (int jk = 0; jk < 8; jk++) {
            unsigned a0 = cvt2(accS[2 * jk][1],     accS[2 * jk][0]);
            unsigned a1 = cvt2(accS[2 * jk][3],     accS[2 * jk][2]);
            unsigned a2 = cvt2(accS[2 * jk + 1][1], accS[2 * jk + 1][0]);
            unsigned a3 = cvt2(accS[2 * jk + 1][3], accS[2 * jk + 1][2]);
#pragma unroll
            for (int dn = 0; dn < 4; dn++) {
                unsigned b0 = vsb[(8 * dn + gid) * 68 + 8 * jk + tig];
                unsigned b1 = vsb[(8 * dn + gid) * 68 + 8 * jk + tig + 4];
                mma_bf16(oacc[dn][0], oacc[dn][1], oacc[dn][2], oacc[dn][3],
                         a0, a1, a2, a3, b0, b1);
            }
        }

        if (jt == 7) break;
        __syncthreads();   // all warps done with buf before refill
        if (jt < 6) {
            stage_kv(ksB[buf], vsB[buf], gk, gvt, (jt + 2) * 128, tid);
            asm volatile("cp.async.commit_group;");
            asm volatile("cp.async.wait_group 1;");
        } else {
            asm volatile("cp.async.wait_group 0;");
        }
        __syncthreads();   // next buffer visible to all warps
    }

    // Epilogue: normalize, write (b, s, c = h*32 + d)
    int b = bh >> 3, h = bh & 7;
    float inv0 = 1.0f / l_0, inv1 = 1.0f / l_1;
    int s0g = (b * 1024 + m0 + r0) * 256 + h * 32;
    int s1g = (b * 1024 + m0 + r1) * 256 + h * 32;
#pragma unroll
    for (int dn = 0; dn < 4; dn++) {
        int d = dn * 8 + 2 * tig;
        g_att[s0g + d]     = oacc[dn][0] * inv0;
        g_att[s0g + d + 1] = oacc[dn][1] * inv0;
        g_att[s1g + d]     = oacc[dn][2] * inv1;
        g_att[s1g + d + 1] = oacc[dn][3] * inv1;
    }
}

// ---------------------------------------------------------------------------
// K6: output projection, bf16 m16n8k16 + ldmatrix, transposed output.
// grid = (8 s-tiles, 2 c-tiles, 16 b)
// ---------------------------------------------------------------------------
__global__ void __launch_bounds__(256) k_oproj(const float* __restrict__ w,
                                               const float* __restrict__ bias,
                                               const float* __restrict__ x,
                                               float* __restrict__ out) {
    __shared__ unsigned Ap[128][20];   // c rows x k2
    __shared__ unsigned Bp[128][20];   // s rows x k2
    int s0 = blockIdx.x * 128;
    int c0 = blockIdx.y * 128;
    int b  = blockIdx.z;
    int tid = threadIdx.x;
    int wid = tid >> 5, lane = tid & 31;
    int gid = lane >> 2, tig = lane & 3;
    int wr = wid & 3, wc = wid >> 2;
    int lm = lane >> 3, lr = lane & 7;

    unsigned aBase = s2u(&Ap[0][0]);
    unsigned bBase = s2u(&Bp[0][0]);
    int aRow = wr * 32 + (lm & 1) * 8 + lr;
    int aCol = 4 * (lm >> 1);
    int bRow = wc * 64 + (lm >> 1) * 8 + lr;
    int bCol = 4 * (lm & 1);

    float acc[2][8][4];
#pragma unroll
    for (int mt = 0; mt < 2; mt++)
#pragma unroll
        for (int nt = 0; nt < 8; nt++)
#pragma unroll
            for (int i = 0; i < 4; i++) acc[mt][nt][i] = 0.0f;

    for (int k0 = 0; k0 < 256; k0 += 32) {
        __syncthreads();
#pragma unroll
        for (int i = 0; i < 4; i++) {
            int idx = tid + i * 256;
            int row = idx >> 3, q = idx & 7;
            float4 v = *(const float4*)&w[(c0 + row) * 256 + k0 + q * 4];
            *(uint2*)&Ap[row][2 * q] = make_uint2(cvt2(v.y, v.x), cvt2(v.w, v.z));
            float4 u = *(const float4*)&g_att[(b * 1024 + s0 + row) * 256 + k0 + q * 4];
            *(uint2*)&Bp[row][2 * q] = make_uint2(cvt2(u.y, u.x), cvt2(u.w, u.z));
        }
        __syncthreads();

#pragma unroll
        for (int dk = 0; dk < 2; dk++) {
            unsigned af[2][4];
#pragma unroll
            for (int mt = 0; mt < 2; mt++)
                ldsm4(af[mt][0], af[mt][1], af[mt][2], af[mt][3],
                      aBase + 4u * ((aRow + mt * 16) * 20 + 8 * dk + aCol));
#pragma unroll
            for (int np = 0; np < 4; np++) {
                unsigned b0a, b1a, b0b, b1b;
                ldsm4(b0a, b1a, b0b, b1b,
                      bBase + 4u * ((bRow + np * 16) * 20 + 8 * dk + bCol));
#pragma unroll
                for (int mt = 0; mt < 2; mt++) {
                    mma_bf16(acc[mt][2 * np][0], acc[mt][2 * np][1],
                             acc[mt][2 * np][2], acc[mt][2 * np][3],
                             af[mt][0], af[mt][1], af[mt][2], af[mt][3], b0a, b1a);
                    mma_bf16(acc[mt][2 * np + 1][0], acc[mt][2 * np + 1][1],
                             acc[mt][2 * np + 1][2], acc[mt][2 * np + 1][3],
                             af[mt][0], af[mt][1], af[mt][2], af[mt][3], b0b, b1b);
                }
            }
        }
    }

#pragma unroll
    for (int mt = 0; mt < 2; mt++) {
        int cg0 = c0 + wr * 32 + mt * 16 + gid;
        int cg1 = cg0 + 8;
        float bv0 = bias[cg0], bv1 = bias[cg1];
#pragma unroll
        for (int nt = 0; nt < 8; nt++) {
            int scol = s0 + wc * 64 + nt * 8 + 2 * tig;
            int idx0 = (b * 256 + cg0) * 1024 + scol;
            int idx1 = (b * 256 + cg1) * 1024 + scol;
            float2 xr0 = *(const float2*)&x[idx0];
            float2 xr1 = *(const float2*)&x[idx1];
            float2 v0 = make_float2(acc[mt][nt][0] + bv0 + xr0.x,
                                    acc[mt][nt][1] + bv0 + xr0.y);
            float2 v1 = make_float2(acc[mt][nt][2] + bv1 + xr1.x,
                                    acc[mt][nt][3] + bv1 + xr1.y);
            *(float2*)&out[idx0] = v0;
            *(float2*)&out[idx1] = v1;
        }
    }
}

// ---------------------------------------------------------------------------
extern "C" void kernel_launch(void* const* d_in, const int* in_sizes, int n_in,
                              void* d_out, int out_size) {
    const float* x      = (const float*)d_in[0];
    const float* t_emb  = (const float*)d_in[1];
    const float* c_emb  = (const float*)d_in[2];
    const float* gn_w   = (const float*)d_in[3];
    const float* gn_b   = (const float*)d_in[4];
    const float* proj_w = (const float*)d_in[5];
    const float* proj_b = (const float*)d_in[6];
    const float* qkv_w  = (const float*)d_in[7];
    const float* qkv_b  = (const float*)d_in[8];
    const float* out_w  = (const float*)d_in[9];
    const float* out_b  = (const float*)d_in[10];
    float* out = (float*)d_out;

    cudaFuncSetAttribute(k_attn, cudaFuncAttributeMaxDynamicSharedMemorySize,
                         SMEM_ATTN);

    k_adaln<<<16, 640>>>(t_emb, c_emb, proj_w, proj_b);
    k_gnstat<<<128, 256>>>(x);
    k_gnapply<<<dim3(32, 16), 256>>>(x, gn_w, gn_b);
    k_qkv<<<dim3(6, 128), 256>>>(qkv_w, qkv_b);
    k_attn<<<dim3(128, 8), 256, SMEM_ATTN>>>();
    k_oproj<<<dim3(8, 2, 16), 256>>>(out_w, out_b, x, out);
}

// round 13
// speedup vs baseline: 1.0847x; 1.0847x over previous
#include <cuda_runtime.h>
#include <cuda_bf16.h>
#include <math.h>

// Problem constants
static const int BB   = 16;
static const int CC   = 256;
static const int SS   = 1024;   // 32*32
static const int NH   = 8;
static const int DKk  = 32;
static const int GR   = 8;
static const int TDIM = 512;
static const int CDIM = 128;
static const int INDIM = 640;   // TDIM + CDIM
static const int TWOC = 512;

// ---- tf32 / bf16 / ldmatrix helpers ----
__device__ __forceinline__ unsigned to_tf32(float f) {
    unsigned r; asm("cvt.rna.tf32.f32 %0, %1;" : "=r"(r) : "f"(f)); return r;
}
// packs {hi, lo} -> bf16x2 register (lo = lower half = first k element)
__device__ __forceinline__ unsigned cvt2(float hi, float lo) {
    unsigned r;
    asm("cvt.rn.bf16x2.f32 %0, %1, %2;" : "=r"(r) : "f"(hi), "f"(lo));
    return r;
}
__device__ __forceinline__ float ex2f(float x) {
    float y; asm("ex2.approx.ftz.f32 %0, %1;" : "=f"(y) : "f"(x)); return y;
}
__device__ __forceinline__ unsigned s2u(const void* p) {
    return (unsigned)__cvta_generic_to_shared(p);
}
__device__ __forceinline__ void ldsm4(unsigned& r0, unsigned& r1,
                                      unsigned& r2, unsigned& r3, unsigned a) {
    asm volatile("ldmatrix.sync.aligned.m8n8.x4.shared.b16 {%0,%1,%2,%3}, [%4];"
                 : "=r"(r0), "=r"(r1), "=r"(r2), "=r"(r3) : "r"(a));
}
__device__ __forceinline__ void mma_tf32(float& d0, float& d1, float& d2, float& d3,
                                         unsigned a0, unsigned a1, unsigned a2, unsigned a3,
                                         unsigned b0, unsigned b1) {
    asm("mma.sync.aligned.m16n8k8.row.col.f32.tf32.tf32.f32 "
        "{%0,%1,%2,%3}, {%4,%5,%6,%7}, {%8,%9}, {%0,%1,%2,%3};"
        : "+f"(d0), "+f"(d1), "+f"(d2), "+f"(d3)
        : "r"(a0), "r"(a1), "r"(a2), "r"(a3), "r"(b0), "r"(b1));
}
__device__ __forceinline__ void mma_bf16(float& d0, float& d1, float& d2, float& d3,
                                         unsigned a0, unsigned a1, unsigned a2, unsigned a3,
                                         unsigned b0, unsigned b1) {
    asm("mma.sync.aligned.m16n8k16.row.col.f32.bf16.bf16.f32 "
        "{%0,%1,%2,%3}, {%4,%5,%6,%7}, {%8,%9}, {%0,%1,%2,%3};"
        : "+f"(d0), "+f"(d1), "+f"(d2), "+f"(d3)
        : "r"(a0), "r"(a1), "r"(a2), "r"(a3), "r"(b0), "r"(b1));
}

// Device scratch
__device__ float g_params[BB * TWOC];
__device__ float g_mean[BB * GR];
__device__ float g_rstd[BB * GR];
__device__ unsigned g_xnp[BB * SS * 128];    // bf16 c-pairs of normalized input
__device__ unsigned g_wqkvp[768 * 128];      // bf16 k-pairs of qkv_w
__device__ unsigned g_wop[256 * 128];        // bf16 k-pairs of out_w
__device__ unsigned g_q[BB * NH * SS * DKk]; // tf32 bits, pre-scaled by 1/sqrt(d)*log2e
__device__ unsigned g_k[BB * NH * SS * DKk]; // tf32 bits
__device__ float    g_v[BB * NH * SS * DKk]; // fp32 (b,h,s,d)
__device__ unsigned g_attp[BB * SS * 128];   // bf16 c-pairs of attention output

// ---------------------------------------------------------------------------
// K0: pack weights to bf16 pairs. grid = 512, block = 256.
// pair p of qkv_w: flat floats [2p, 2p+1]; same for out_w.
// ---------------------------------------------------------------------------
__global__ void k_pack(const float* __restrict__ qkv_w,
                       const float* __restrict__ out_w) {
    int idx = blockIdx.x * 256 + threadIdx.x;   // 0..131071
    if (idx < 98304) {
        float2 v = *(const float2*)&qkv_w[idx * 2];
        g_wqkvp[idx] = cvt2(v.y, v.x);
    } else {
        int p = idx - 98304;
        float2 v = *(const float2*)&out_w[p * 2];
        g_wop[p] = cvt2(v.y, v.x);
    }
}

// ---------------------------------------------------------------------------
// K1: adaLN projection. grid = 16, block = 640
// ---------------------------------------------------------------------------
__global__ void k_adaln(const float* __restrict__ t_emb,
                        const float* __restrict__ c_emb,
                        const float* __restrict__ pw,
                        const float* __restrict__ pb) {
    __shared__ float sin_[INDIM];
    int b = blockIdx.x;
    int t = threadIdx.x;
    float v = (t < TDIM) ? t_emb[b * TDIM + t] : c_emb[b * CDIM + (t - TDIM)];
    sin_[t] = v / (1.0f + expf(-v));
    __syncthreads();
    if (t < TWOC) {
        const float* wr = pw + t * INDIM;
        float acc = pb[t];
#pragma unroll 8
        for (int i = 0; i < INDIM; i++) acc += sin_[i] * wr[i];
        g_params[b * TWOC + t] = acc;
    }
}

// ---------------------------------------------------------------------------
// K2: GroupNorm statistics. grid = 128, block = 256
// ---------------------------------------------------------------------------
__global__ void k_gnstat(const float* __restrict__ x) {
    int bg = blockIdx.x;
    const float4* p = (const float4*)(x + (size_t)bg * 32768);
    float s = 0.0f, ss = 0.0f;
    for (int i = threadIdx.x; i < 8192; i += 256) {
        float4 v = p[i];
        s  += v.x + v.y + v.z + v.w;
        ss += v.x * v.x + v.y * v.y + v.z * v.z + v.w * v.w;
    }
#pragma unroll
    for (int o = 16; o; o >>= 1) {
        s  += __shfl_xor_sync(0xffffffffu, s, o);
        ss += __shfl_xor_sync(0xffffffffu, ss, o);
    }
    __shared__ float rs[8], rss[8];
    int w = threadIdx.x >> 5, l = threadIdx.x & 31;
    if (l == 0) { rs[w] = s; rss[w] = ss; }
    __syncthreads();
    if (threadIdx.x == 0) {
        float S = 0.0f, SSum = 0.0f;
#pragma unroll
        for (int i = 0; i < 8; i++) { S += rs[i]; SSum += rss[i]; }
        float m = S / 32768.0f;
        float var = SSum / 32768.0f - m * m;
        g_mean[bg] = m;
        g_rstd[bg] = rsqrtf(var + 1e-6f);
    }
}

// ---------------------------------------------------------------------------
// K3: apply GN + adaLN affine, transpose (b,c,s) -> packed bf16 (b,s,c-pairs).
// grid = (32 s-tiles, 16 b), block = 256.
// ---------------------------------------------------------------------------
__global__ void k_gnapply(const float* __restrict__ x,
                          const float* __restrict__ gw,
                          const float* __restrict__ gb) {
    __shared__ float tile[CC][33];
    int b = blockIdx.y;
    int s0 = blockIdx.x * 32;
    int t = threadIdx.x;
    int w = t >> 5, sl = t & 31;
#pragma unroll
    for (int k = 0; k < 32; k++) {
        int c = k * 8 + w;
        float v = x[(b * CC + c) * SS + s0 + sl];
        int g = c >> 5;
        float vn = (v - g_mean[b * GR + g]) * g_rstd[b * GR + g];
        vn = vn * gw[c] + gb[c];
        float gam = g_params[b * TWOC + c];
        float bet = g_params[b * TWOC + CC + c];
        tile[c][sl] = vn * (1.0f + gam) + bet;
    }
    __syncthreads();
    int hi = t >> 7, c2 = t & 127;
#pragma unroll
    for (int k = 0; k < 16; k++) {
        int row = hi * 16 + k;
        g_xnp[(b * 1024 + s0 + row) * 128 + c2] =
            cvt2(tile[2 * c2 + 1][row], tile[2 * c2][row]);
    }
}

// ---------------------------------------------------------------------------
// K4: QKV GEMM, bf16 m16n8k16 + ldmatrix; pre-packed inputs (raw copies).
// Epilogue: Q -> pre-scaled tf32 bits, K -> tf32 bits, V -> fp32.
// grid = (6, 128)
// ---------------------------------------------------------------------------
__global__ void __launch_bounds__(256) k_qkv(const float* __restrict__ bias) {
    __shared__ unsigned Ap[128][20];
    __shared__ unsigned Bp[128][20];
    int m0 = blockIdx.y * 128;
    int o0 = blockIdx.x * 128;
    int tid = threadIdx.x;
    int wid = tid >> 5, lane = tid & 31;
    int gid = lane >> 2, tig = lane & 3;
    int wr = wid & 3, wc = wid >> 2;
    int lm = lane >> 3, lr = lane & 7;

    unsigned aBase = s2u(&Ap[0][0]);
    unsigned bBase = s2u(&Bp[0][0]);
    int aRow = wr * 32 + (lm & 1) * 8 + lr;
    int aCol = 4 * (lm >> 1);
    int bRow = wc * 64 + (lm >> 1) * 8 + lr;
    int bCol = 4 * (lm & 1);

    float acc[2][8][4];
#pragma unroll
    for (int mt = 0; mt < 2; mt++)
#pragma unroll
        for (int nt = 0; nt < 8; nt++)
#pragma unroll
            for (int i = 0; i < 4; i++) acc[mt][nt][i] = 0.0f;

    for (int k0h = 0; k0h < 128; k0h += 16) {   // k-pair chunks of 16
        __syncthreads();
#pragma unroll
        for (int i = 0; i < 2; i++) {
            int idx = tid + i * 256;            // 0..511
            int row = idx >> 2, q4 = idx & 3;
            *(uint4*)&Ap[row][4 * q4] =
                *(const uint4*)&g_xnp[(m0 + row) * 128 + k0h + 4 * q4];
            *(uint4*)&Bp[row][4 * q4] =
                *(const uint4*)&g_wqkvp[(o0 + row) * 128 + k0h + 4 * q4];
        }
        __syncthreads();

#pragma unroll
        for (int dk = 0; dk < 2; dk++) {
            unsigned af[2][4];
#pragma unroll
            for (int mt = 0; mt < 2; mt++)
                ldsm4(af[mt][0], af[mt][1], af[mt][2], af[mt][3],
                      aBase + 4u * ((aRow + mt * 16) * 20 + 8 * dk + aCol));
#pragma unroll
            for (int np = 0; np < 4; np++) {
                unsigned b0a, b1a, b0b, b1b;
                ldsm4(b0a, b1a, b0b, b1b,
                      bBase + 4u * ((bRow + np * 16) * 20 + 8 * dk + bCol));
#pragma unroll
                for (int mt = 0; mt < 2; mt++) {
                    mma_bf16(acc[mt][2 * np][0], acc[mt][2 * np][1],
                             acc[mt][2 * np][2], acc[mt][2 * np][3],
                             af[mt][0], af[mt][1], af[mt][2], af[mt][3], b0a, b1a);
                    mma_bf16(acc[mt][2 * np + 1][0], acc[mt][2 * np + 1][1],
                             acc[mt][2 * np + 1][2], acc[mt][2 * np + 1][3],
                             af[mt][0], af[mt][1], af[mt][2], af[mt][3], b0b, b1b);
                }
            }
        }
    }

    int b = m0 >> 10;
    const float qsc = 0.17677669529663687f * 1.4426950408889634f;
#pragma unroll
    for (int mt = 0; mt < 2; mt++) {
        int s_0 = (m0 + wr * 32 + mt * 16 + gid) & 1023;
        int s_1 = s_0 + 8;
#pragma unroll
        for (int nt = 0; nt < 8; nt++) {
            int bcol = wc * 64 + nt * 8 + 2 * tig;   // 0..127
            float bx = bias[o0 + bcol];
            float by = bias[o0 + bcol + 1];
            float v00 = acc[mt][nt][0] + bx, v01 = acc[mt][nt][1] + by;
            float v10 = acc[mt][nt][2] + bx, v11 = acc[mt][nt][3] + by;
            if (o0 < 256) {
                int lcol = o0 + bcol;
                int h = lcol >> 5, d = lcol & 31;
                uint2 u0 = make_uint2(to_tf32(v00 * qsc), to_tf32(v01 * qsc));
                uint2 u1 = make_uint2(to_tf32(v10 * qsc), to_tf32(v11 * qsc));
                *(uint2*)&g_q[((b * 8 + h) * 1024 + s_0) * 32 + d] = u0;
                *(uint2*)&g_q[((b * 8 + h) * 1024 + s_1) * 32 + d] = u1;
            } else if (o0 < 512) {
                int lcol = o0 - 256 + bcol;
                int h = lcol >> 5, d = lcol & 31;
                uint2 u0 = make_uint2(to_tf32(v00), to_tf32(v01));
                uint2 u1 = make_uint2(to_tf32(v10), to_tf32(v11));
                *(uint2*)&g_k[((b * 8 + h) * 1024 + s_0) * 32 + d] = u0;
                *(uint2*)&g_k[((b * 8 + h) * 1024 + s_1) * 32 + d] = u1;
            } else {
                int lcol = o0 - 512 + bcol;
                int h = lcol >> 5, d = lcol & 31;
                *(float2*)&g_v[((b * 8 + h) * 1024 + s_0) * 32 + d] =
                    make_float2(v00, v01);
                *(float2*)&g_v[((b * 8 + h) * 1024 + s_1) * 32 + d] =
                    make_float2(v10, v11);
            }
        }
    }
}

// ---------------------------------------------------------------------------
// K5: flash attention (R10 structure). Q/K pre-converted tf32 (raw copies),
// base-2 softmax, Phase C bf16 with register P; V packed per tile from fp32.
// grid = (128 bh, 8 q-tiles), 256 thr, 46KB static smem.
// ---------------------------------------------------------------------------
__global__ void __launch_bounds__(256) k_attn() {
    __shared__ unsigned qs[128][36];     // tf32 Q (pre-scaled)
    __shared__ unsigned ks[128][36];     // tf32 K
    __shared__ unsigned vpack[64][40];   // bf16x2 {V[2j2+1], V[2j2]} at col d

    int bh = blockIdx.x;
    int m0 = blockIdx.y * 128;
    int tid = threadIdx.x;
    int w = tid >> 5, lane = tid & 31;
    int gid = lane >> 2, tig = lane & 3;
    int lm = lane >> 3, lr = lane & 7;
    int base = bh * (1024 * 32);
    int r0 = 16 * w + gid;
    int r1 = r0 + 8;

    unsigned ksBase = s2u(&ks[0][0]);
    int kRow = 8 * (lm >> 1) + lr;
    int kCol = 4 * (lm & 1);

    // Load Q tile (pre-scaled tf32, raw copy)
#pragma unroll
    for (int i = 0; i < 4; i++) {
        int idx = tid + i * 256;
        int row = idx >> 3, dq = idx & 7;
        *(uint4*)&qs[row][dq * 4] =
            *(const uint4*)&g_q[base + (m0 + row) * 32 + dq * 4];
    }
    __syncthreads();

    unsigned qa[4][4];
#pragma unroll
    for (int dk = 0; dk < 4; dk++) {
        qa[dk][0] = qs[r0][8 * dk + tig];
        qa[dk][1] = qs[r1][8 * dk + tig];
        qa[dk][2] = qs[r0][8 * dk + tig + 4];
        qa[dk][3] = qs[r1][8 * dk + tig + 4];
    }

    float m_0 = -1e30f, m_1 = -1e30f, l_0 = 0.0f, l_1 = 0.0f;
    float oacc[4][4];
#pragma unroll
    for (int dn = 0; dn < 4; dn++)
#pragma unroll
        for (int i = 0; i < 4; i++) oacc[dn][i] = 0.0f;

    for (int j0 = 0; j0 < 1024; j0 += 128) {
        __syncthreads();   // previous tile's ks/vpack fully consumed
        // K raw copy (already tf32)
#pragma unroll
        for (int i = 0; i < 4; i++) {
            int idx = tid + i * 256;
            int row = idx >> 3, dq = idx & 7;
            *(uint4*)&ks[row][dq * 4] =
                *(const uint4*)&g_k[base + (j0 + row) * 32 + dq * 4];
        }
        // V packed bf16 j-pairs via float4 loads + STS.128
#pragma unroll
        for (int i = 0; i < 2; i++) {
            int item = tid + i * 256;          // 0..511
            int j2 = item >> 3, dq = item & 7;
            float4 v0 = *(const float4*)&g_v[base + (j0 + 2 * j2) * 32 + dq * 4];
            float4 v1 = *(const float4*)&g_v[base + (j0 + 2 * j2 + 1) * 32 + dq * 4];
            uint4 pk;
            pk.x = cvt2(v1.x, v0.x); pk.y = cvt2(v1.y, v0.y);
            pk.z = cvt2(v1.z, v0.z); pk.w = cvt2(v1.w, v0.w);
            *(uint4*)&vpack[j2][dq * 4] = pk;
        }
        __syncthreads();

        // Phase A: S = Q K^T (tf32, ldmatrix K fragments)
        float accS[16][4];
#pragma unroll
        for (int jp = 0; jp < 8; jp++) {
            int ja = 2 * jp, jb = 2 * jp + 1;
            accS[ja][0] = accS[ja][1] = accS[ja][2] = accS[ja][3] = 0.0f;
            accS[jb][0] = accS[jb][1] = accS[jb][2] = accS[jb][3] = 0.0f;
#pragma unroll
            for (int dk = 0; dk < 4; dk++) {
                unsigned b0a, b1a, b0b, b1b;
                ldsm4(b0a, b1a, b0b, b1b,
                      ksBase + 4u * ((16 * jp + kRow) * 36 + 8 * dk + kCol));
                mma_tf32(accS[ja][0], accS[ja][1], accS[ja][2], accS[ja][3],
                         qa[dk][0], qa[dk][1], qa[dk][2], qa[dk][3], b0a, b1a);
                mma_tf32(accS[jb][0], accS[jb][1], accS[jb][2], accS[jb][3],
                         qa[dk][0], qa[dk][1], qa[dk][2], qa[dk][3], b0b, b1b);
            }
        }

        // Phase B: online softmax, base 2 (Q carries log2e)
        float mx0 = -1e30f, mx1 = -1e30f;
#pragma unroll
        for (int jn = 0; jn < 16; jn++) {
            mx0 = fmaxf(mx0, fmaxf(accS[jn][0], accS[jn][1]));
            mx1 = fmaxf(mx1, fmaxf(accS[jn][2], accS[jn][3]));
        }
        mx0 = fmaxf(mx0, __shfl_xor_sync(0xffffffffu, mx0, 1));
        mx0 = fmaxf(mx0, __shfl_xor_sync(0xffffffffu, mx0, 2));
        mx1 = fmaxf(mx1, __shfl_xor_sync(0xffffffffu, mx1, 1));
        mx1 = fmaxf(mx1, __shfl_xor_sync(0xffffffffu, mx1, 2));
        float mn0 = fmaxf(m_0, mx0), mn1 = fmaxf(m_1, mx1);
        float corr0 = ex2f(m_0 - mn0), corr1 = ex2f(m_1 - mn1);
        float sum0 = 0.0f, sum1 = 0.0f;
#pragma unroll
        for (int jn = 0; jn < 16; jn++) {
            float p00 = ex2f(accS[jn][0] - mn0);
            float p01 = ex2f(accS[jn][1] - mn0);
            float p10 = ex2f(accS[jn][2] - mn1);
            float p11 = ex2f(accS[jn][3] - mn1);
            sum0 += p00 + p01;
            sum1 += p10 + p11;
            accS[jn][0] = p00; accS[jn][1] = p01;
            accS[jn][2] = p10; accS[jn][3] = p11;
        }
        sum0 += __shfl_xor_sync(0xffffffffu, sum0, 1);
        sum0 += __shfl_xor_sync(0xffffffffu, sum0, 2);
        sum1 += __shfl_xor_sync(0xffffffffu, sum1, 1);
        sum1 += __shfl_xor_sync(0xffffffffu, sum1, 2);
        l_0 = l_0 * corr0 + sum0;
        l_1 = l_1 * corr1 + sum1;
        m_0 = mn0; m_1 = mn1;
#pragma unroll
        for (int dn = 0; dn < 4; dn++) {
            oacc[dn][0] *= corr0; oacc[dn][1] *= corr0;
            oacc[dn][2] *= corr1; oacc[dn][3] *= corr1;
        }

        // Phase C: O += P V (bf16 m16n8k16, P repacked in registers)
#pragma unroll
        for (int jk = 0; jk < 8; jk++) {
            unsigned a0 = cvt2(accS[2 * jk][1],     accS[2 * jk][0]);
            unsigned a1 = cvt2(accS[2 * jk][3],     accS[2 * jk][2]);
            unsigned a2 = cvt2(accS[2 * jk + 1][1], accS[2 * jk + 1][0]);
            unsigned a3 = cvt2(accS[2 * jk + 1][3], accS[2 * jk + 1][2]);
#pragma unroll
            for (int dn = 0; dn < 4; dn++) {
                unsigned b0 = vpack[8 * jk + tig][8 * dn + gid];
                unsigned b1 = vpack[8 * jk + tig + 4][8 * dn + gid];
                mma_bf16(oacc[dn][0], oacc[dn][1], oacc[dn][2], oacc[dn][3],
                         a0, a1, a2, a3, b0, b1);
            }
        }
    }

    // Epilogue: normalize, write bf16 c-pairs (same rounding oproj applied)
    int b = bh >> 3, h = bh & 7;
    float inv0 = 1.0f / l_0, inv1 = 1.0f / l_1;
    int p0g = (b * 1024 + m0 + r0) * 128 + h * 16;
    int p1g = (b * 1024 + m0 + r1) * 128 + h * 16;
#pragma unroll
    for (int dn = 0; dn < 4; dn++) {
        int c2 = dn * 4 + tig;
        g_attp[p0g + c2] = cvt2(oacc[dn][1] * inv0, oacc[dn][0] * inv0);
        g_attp[p1g + c2] = cvt2(oacc[dn][3] * inv1, oacc[dn][2] * inv1);
    }
}

// ---------------------------------------------------------------------------
// K6: output projection, bf16 m16n8k16 + ldmatrix, pre-packed inputs,
// transposed output. grid = (8 s-tiles, 2 c-tiles, 16 b)
// ---------------------------------------------------------------------------
__global__ void __launch_bounds__(256) k_oproj(const float* __restrict__ bias,
                                               const float* __restrict__ x,
                                               float* __restrict__ out) {
    __shared__ unsigned Ap[128][20];   // c rows x k2
    __shared__ unsigned Bp[128][20];   // s rows x k2
    int s0 = blockIdx.x * 128;
    int c0 = blockIdx.y * 128;
    int b  = blockIdx.z;
    int tid = threadIdx.x;
    int wid = tid >> 5, lane = tid & 31;
    int gid = lane >> 2, tig = lane & 3;
    int wr = wid & 3, wc = wid >> 2;
    int lm = lane >> 3, lr = lane & 7;

    unsigned aBase = s2u(&Ap[0][0]);
    unsigned bBase = s2u(&Bp[0][0]);
    int aRow = wr * 32 + (lm & 1) * 8 + lr;
    int aCol = 4 * (lm >> 1);
    int bRow = wc * 64 + (lm >> 1) * 8 + lr;
    int bCol = 4 * (lm & 1);

    float acc[2][8][4];
#pragma unroll
    for (int mt = 0; mt < 2; mt++)
#pragma unroll
        for (int nt = 0; nt < 8; nt++)
#pragma unroll
            for (int i = 0; i < 4; i++) acc[mt][nt][i] = 0.0f;

    for (int k0h = 0; k0h < 128; k0h += 16) {
        __syncthreads();
#pragma unroll
        for (int i = 0; i < 2; i++) {
            int idx = tid + i * 256;
            int row = idx >> 2, q4 = idx & 3;
            *(uint4*)&Ap[row][4 * q4] =
                *(const uint4*)&g_wop[(c0 + row) * 128 + k0h + 4 * q4];
            *(uint4*)&Bp[row][4 * q4] =
                *(const uint4*)&g_attp[(b * 1024 + s0 + row) * 128 + k0h + 4 * q4];
        }
        __syncthreads();

#pragma unroll
        for (int dk = 0; dk < 2; dk++) {
            unsigned af[2][4];
#pragma unroll
            for (int mt = 0; mt < 2; mt++)
                ldsm4(af[mt][0], af[mt][1], af[mt][2], af[mt][3],
                      aBase + 4u * ((aRow + mt * 16) * 20 + 8 * dk + aCol));
#pragma unroll
            for (int np = 0; np < 4; np++) {
                unsigned b0a, b1a, b0b, b1b;
                ldsm4(b0a, b1a, b0b, b1b,
                      bBase + 4u * ((bRow + np * 16) * 20 + 8 * dk + bCol));
#pragma unroll
                for (int mt = 0; mt < 2; mt++) {
                    mma_bf16(acc[mt][2 * np][0], acc[mt][2 * np][1],
                             acc[mt][2 * np][2], acc[mt][2 * np][3],
                             af[mt][0], af[mt][1], af[mt][2], af[mt][3], b0a, b1a);
                    mma_bf16(acc[mt][2 * np + 1][0], acc[mt][2 * np + 1][1],
                             acc[mt][2 * np + 1][2], acc[mt][2 * np + 1][3],
                             af[mt][0], af[mt][1], af[mt][2], af[mt][3], b0b, b1b);
                }
            }
        }
    }

#pragma unroll
    for (int mt = 0; mt < 2; mt++) {
        int cg0 = c0 + wr * 32 + mt * 16 + gid;
        int cg1 = cg0 + 8;
        float bv0 = bias[cg0], bv1 = bias[cg1];
#pragma unroll
        for (int nt = 0; nt < 8; nt++) {
            int scol = s0 + wc * 64 + nt * 8 + 2 * tig;
            int idx0 = (b * 256 + cg0) * 1024 + scol;
            int idx1 = (b * 256 + cg1) * 1024 + scol;
            float2 xr0 = *(const float2*)&x[idx0];
            float2 xr1 = *(const float2*)&x[idx1];
            float2 v0 = make_float2(acc[mt][nt][0] + bv0 + xr0.x,
                                    acc[mt][nt][1] + bv0 + xr0.y);
            float2 v1 = make_float2(acc[mt][nt][2] + bv1 + xr1.x,
                                    acc[mt][nt][3] + bv1 + xr1.y);
            *(float2*)&out[idx0] = v0;
            *(float2*)&out[idx1] = v1;
        }
    }
}

// ---------------------------------------------------------------------------
extern "C" void kernel_launch(void* const* d_in, const int* in_sizes, int n_in,
                              void* d_out, int out_size) {
    const float* x      = (const float*)d_in[0];
    const float* t_emb  = (const float*)d_in[1];
    const float* c_emb  = (const float*)d_in[2];
    const float* gn_w   = (const float*)d_in[3];
    const float* gn_b   = (const float*)d_in[4];
    const float* proj_w = (const float*)d_in[5];
    const float* proj_b = (const float*)d_in[6];
    const float* qkv_w  = (const float*)d_in[7];
    const float* qkv_b  = (const float*)d_in[8];
    const float* out_w  = (const float*)d_in[9];
    const float* out_b  = (const float*)d_in[10];
    float* out = (float*)d_out;

    k_pack<<<512, 256>>>(qkv_w, out_w);
    k_adaln<<<16, 640>>>(t_emb, c_emb, proj_w, proj_b);
    k_gnstat<<<128, 256>>>(x);
    k_gnapply<<<dim3(32, 16), 256>>>(x, gn_w, gn_b);
    k_qkv<<<dim3(6, 128), 256>>>(qkv_b);
    k_attn<<<dim3(128, 8), 256>>>();
    k_oproj<<<dim3(8, 2, 16), 256>>>(out_b, x, out);
}